// round 15
// baseline (speedup 1.0000x reference)
#include <cuda_runtime.h>
#include <cuda_fp16.h>
#include <cstdint>
#include <cfloat>

// Problem constants
#define NF    1024
#define BATCH 1024
#define HW    64
#define PIX   (HW * HW)     // 4096
#define PAD   3
#define PW    70            // padded side
#define PPIX  (PW * PW)     // 4900
#define FHALF 512           // filters per constant-bank pass

// 10 MB scratch: zero-PADDED image, fp16, transposed to [padded_pixel][batch].
// __device__ globals are zero-initialized at module load (fp16 zero == 0x0000)
// and the transpose never writes the 3-wide border, so the conv loop needs no
// bounds checks, no border kernel, and no per-load address math.
__device__ __half g_xh[(size_t)PPIX * BATCH];

// Per-pass constant bank: 512 filters of weights + bias (53.2 KB < 64 KB).
// Re-filled between the two conv launches via stream-ordered D2D memcpy.
// Uniform (blockIdx-derived) indexing -> LDCU -> uniform registers -> the
// weight operand of FFMA2 stays OUT of the GPR read banks (rt 3 -> 2).
__constant__ float c_w[FHALF * 25];
__constant__ float c_b[FHALF];

// ---------------------------------------------------------------------------
// Kernel 1: transpose + fp32->fp16 convert.  X [B, 4096] -> g_xh interior.
// ---------------------------------------------------------------------------
__global__ void xt_transpose_kernel(const float* __restrict__ X) {
    __shared__ float tile[32][65];          // [pixel_local][batch_local]
    const int p0 = blockIdx.x * 32;
    const int b0 = blockIdx.y * 64;
    const int tx = threadIdx.x;             // block (32, 8)
    const int ty = threadIdx.y;

#pragma unroll
    for (int k = 0; k < 64; k += 8)         // coalesced 128B loads
        tile[tx][ty + k] = X[(size_t)(b0 + ty + k) * PIX + (p0 + tx)];
    __syncthreads();

    const int w = ty;
#pragma unroll
    for (int i = 0; i < 4; i++) {
        const int pl = w * 4 + i;
        const int p  = p0 + pl;
        const int y  = p >> 6, x = p & 63;
        const __half2 v = __floats2half2_rn(tile[pl][2 * tx],
                                            tile[pl][2 * tx + 1]);
        *(__half2*)(g_xh + (size_t)((y + PAD) * PW + (x + PAD)) * BATCH
                         + b0 + 2 * tx) = v;
    }
}

// ---------------------------------------------------------------------------
// Packed f32x2 helpers (Blackwell packed-FP32 pipe)
// ---------------------------------------------------------------------------
__device__ __forceinline__ unsigned long long ffma2(unsigned long long a,
                                                    unsigned long long b,
                                                    unsigned long long c) {
    unsigned long long d;
    asm("fma.rn.f32x2 %0, %1, %2, %3;" : "=l"(d) : "l"(a), "l"(b), "l"(c));
    return d;
}
__device__ __forceinline__ unsigned long long fmul2(unsigned long long a,
                                                    unsigned long long b) {
    unsigned long long d;
    asm("mul.rn.f32x2 %0, %1, %2;" : "=l"(d) : "l"(a), "l"(b));
    return d;
}
__device__ __forceinline__ unsigned long long pack2(float x, float y) {
    unsigned long long r;
    asm("mov.b64 %0, {%1, %2};" : "=l"(r) : "f"(x), "f"(y));
    return r;
}
__device__ __forceinline__ float2 unpack2(unsigned long long v) {
    float2 r;
    asm("mov.b64 {%0, %1}, %2;" : "=f"(r.x), "=f"(r.y) : "l"(v));
    return r;
}

// ---------------------------------------------------------------------------
// Kernel 2: per (filter, batch-pair) fused 5x5 conv (the 6x6 of the 7x7
// outputs the pool reads) + bias + 3x3/3 maxpool.  Single 6-wide pass with
// early pool-fold (<=30 packed accumulators live).  Weights come from the
// __constant__ bank with a block-uniform index so their FFMA2 operand can
// live in uniform registers (breaks the 3-cycle GPR-bank floor).
// ---------------------------------------------------------------------------
__global__ void __launch_bounds__(128, 4) filters_conv_kernel(
    const int* __restrict__ pos,      // [NF, 2]
    float*     __restrict__ out,      // [B, NF*4]
    int        half)                  // 0: filters 0-511, 1: 512-1023
{
    const int fl = blockIdx.x;                  // filter index in this pass
    const int f  = half * FHALF + fl;           // global filter index
    const int tid = threadIdx.x;
    const int b = blockIdx.y * 256 + tid * 2;   // even -> 4B aligned
    const int pi = __ldg(&pos[2 * f]);
    const int pj = __ldg(&pos[2 * f + 1]);

    // Window base pointer; all loads below use compile-time byte offsets.
    const char* p0 = (const char*)g_xh +
                     ((size_t)(pi * PW + pj) * BATCH + b) * sizeof(__half);

    unsigned long long acc[36];              // <=30 live at any point
    float pm0[4], pm1[4];                    // running 2x2 max per batch
#pragma unroll
    for (int q = 0; q < 4; q++) { pm0[q] = -FLT_MAX; pm1[q] = -FLT_MAX; }

    // Stream the 10 window rows of the zero-padded fp16 image.
#pragma unroll
    for (int r = 0; r < 10; r++) {
        unsigned long long row[10];
#pragma unroll
        for (int c = 0; c < 10; c++) {
            const __half2 h = *(const __half2*)(
                p0 + (size_t)((r * PW + c) * BATCH) * sizeof(__half));
            const float2 fv = __half22float2(h);
            row[c] = pack2(fv.x, fv.y);
        }

        // Row r feeds conv rows oy with ky = r - oy in [0,4].
#pragma unroll
        for (int oy = 0; oy < 6; oy++) {
            const int ky = r - oy;
            if (ky < 0 || ky > 4) continue;       // compile-time pruned
#pragma unroll
            for (int kx = 0; kx < 5; kx++) {
                // Uniform constant load; (w, w) pair is warp-uniform.
                const float ws = c_w[fl * 25 + ky * 5 + kx];
                const unsigned long long w = pack2(ws, ws);
#pragma unroll
                for (int ox = 0; ox < 6; ox++) {
                    if (ky == 0 && kx == 0)
                        acc[oy * 6 + ox] = fmul2(row[ox], w);
                    else
                        acc[oy * 6 + ox] = ffma2(row[ox + kx], w,
                                                 acc[oy * 6 + ox]);
                }
            }
        }

        // Conv row oy = r-4 complete: fold into pooled max, free its accs.
        if (r >= 4) {
            const int oy = r - 4;
            const int py = oy / 3;               // compile-time
#pragma unroll
            for (int px = 0; px < 2; px++) {
#pragma unroll
                for (int dx = 0; dx < 3; dx++) {
                    const float2 v = unpack2(acc[oy * 6 + 3 * px + dx]);
                    pm0[py * 2 + px] = fmaxf(pm0[py * 2 + px], v.x);
                    pm1[py * 2 + px] = fmaxf(pm1[py * 2 + px], v.y);
                }
            }
        }
    }

    // bias (uniform -> add after max) and one float4 store per batch.
    const float bv = c_b[fl];
    float4* o0 = (float4*)(out + (size_t)b * (NF * 4) + f * 4);
    float4* o1 = (float4*)(out + (size_t)(b + 1) * (NF * 4) + f * 4);
    *o0 = make_float4(pm0[0] + bv, pm0[1] + bv, pm0[2] + bv, pm0[3] + bv);
    *o1 = make_float4(pm1[0] + bv, pm1[1] + bv, pm1[2] + bv, pm1[3] + bv);
}

// ---------------------------------------------------------------------------
// kernel_launch: transpose, then two (copy-constants -> conv) passes.  All
// stream-ordered on the default stream: each D2D symbol copy waits for the
// previous conv to finish reading the bank.  Graph-capturable (async D2D
// memcpys + kernel launches only), allocation-free, deterministic.
// ---------------------------------------------------------------------------
extern "C" void kernel_launch(void* const* d_in, const int* in_sizes, int n_in,
                              void* d_out, int out_size) {
    (void)in_sizes; (void)n_in; (void)out_size;
    const float* X    = (const float*)d_in[0];
    const float* W    = (const float*)d_in[1];
    const float* bias = (const float*)d_in[2];
    const int*   pos  = (const int*)d_in[3];
    float*       out  = (float*)d_out;

    dim3 tb(32, 8);
    dim3 tg(PIX / 32, BATCH / 64);         // (128, 16)
    xt_transpose_kernel<<<tg, tb>>>(X);

    for (int h = 0; h < 2; h++) {
        cudaMemcpyToSymbolAsync(c_w, W + (size_t)h * FHALF * 25,
                                FHALF * 25 * sizeof(float), 0,
                                cudaMemcpyDeviceToDevice);
        cudaMemcpyToSymbolAsync(c_b, bias + (size_t)h * FHALF,
                                FHALF * sizeof(float), 0,
                                cudaMemcpyDeviceToDevice);
        dim3 cg(FHALF, BATCH / 256);       // (512, 4)
        filters_conv_kernel<<<cg, 128>>>(pos, out, h);
    }
}